// round 8
// baseline (speedup 1.0000x reference)
#include <cuda_runtime.h>

#define CB 4
#define CS 2048
#define CD 1024
#define CH 16
#define CDH 64

// Scratch (static __device__ globals: the sanctioned no-alloc workaround).
__device__ float g_q[CB * CH * CS * CDH];   // (B,H,S,DH)
__device__ float g_k[CB * CH * CS * CDH];
__device__ float g_v[CB * CH * CS * CDH];
__device__ float g_o[CB * CS * CD];         // attention out, (B,S,D)

__device__ __forceinline__ float to_tf32(float x) {
    unsigned u;
    asm("cvt.rna.tf32.f32 %0, %1;" : "=r"(u) : "f"(x));
    return __uint_as_float(u);
}

__device__ __forceinline__ void mma_tf32(float c[4], unsigned a0, unsigned a1,
                                         unsigned a2, unsigned a3,
                                         unsigned b0, unsigned b1) {
    asm volatile(
        "mma.sync.aligned.m16n8k8.row.col.f32.tf32.tf32.f32 "
        "{%0,%1,%2,%3}, {%4,%5,%6,%7}, {%8,%9}, {%0,%1,%2,%3};\n"
        : "+f"(c[0]), "+f"(c[1]), "+f"(c[2]), "+f"(c[3])
        : "r"(a0), "r"(a1), "r"(a2), "r"(a3), "r"(b0), "r"(b1));
}

// ---------------------------------------------------------------------------
// tf32 tensor-core GEMM (unchanged from R3/R4 passing kernel).
// ---------------------------------------------------------------------------
template <int LAYOUT>
__device__ __forceinline__ void gemm_tf32(
    const float* __restrict__ A, const float* __restrict__ W,
    const float* __restrict__ bias, float* __restrict__ out)
{
    __shared__ float As[2][16][136];
    __shared__ float Bs[2][16][136];

    const int tid = threadIdx.x;
    const int m0 = blockIdx.y * 128;
    const int n0 = blockIdx.x * 128;

    const int arow  = tid & 127;
    const int acol  = (tid >> 7) * 8;
    const int wkr   = tid >> 4;
    const int wnc   = (tid & 15) * 8;

    const float* Ap = A + (size_t)(m0 + arow) * CD + acol;
    const float* Wp = W + (size_t)wkr * CD + n0 + wnc;

    {
        float4 a0v = *(const float4*)(Ap);
        float4 a1v = *(const float4*)(Ap + 4);
        float4 b0v = *(const float4*)(Wp);
        float4 b1v = *(const float4*)(Wp + 4);
        As[0][acol + 0][arow] = to_tf32(a0v.x);
        As[0][acol + 1][arow] = to_tf32(a0v.y);
        As[0][acol + 2][arow] = to_tf32(a0v.z);
        As[0][acol + 3][arow] = to_tf32(a0v.w);
        As[0][acol + 4][arow] = to_tf32(a1v.x);
        As[0][acol + 5][arow] = to_tf32(a1v.y);
        As[0][acol + 6][arow] = to_tf32(a1v.z);
        As[0][acol + 7][arow] = to_tf32(a1v.w);
        float4 t0 = make_float4(to_tf32(b0v.x), to_tf32(b0v.y), to_tf32(b0v.z), to_tf32(b0v.w));
        float4 t1 = make_float4(to_tf32(b1v.x), to_tf32(b1v.y), to_tf32(b1v.z), to_tf32(b1v.w));
        *(float4*)&Bs[0][wkr][wnc]     = t0;
        *(float4*)&Bs[0][wkr][wnc + 4] = t1;
    }
    __syncthreads();

    const int wid    = tid >> 5;
    const int lane   = tid & 31;
    const int warp_m = (wid >> 2) * 64;
    const int warp_n = (wid & 3) * 32;
    const int g = lane >> 2;
    const int t = lane & 3;

    float c[4][4][4];
#pragma unroll
    for (int mt = 0; mt < 4; mt++)
#pragma unroll
        for (int nt = 0; nt < 4; nt++)
#pragma unroll
            for (int r = 0; r < 4; r++) c[mt][nt][r] = 0.f;

    int buf = 0;
    for (int kt = 0; kt < 64; kt++) {
        float4 a0v, a1v, b0v, b1v;
        if (kt < 63) {
            a0v = *(const float4*)(Ap + (kt + 1) * 16);
            a1v = *(const float4*)(Ap + (kt + 1) * 16 + 4);
            b0v = *(const float4*)(Wp + (size_t)(kt + 1) * 16 * CD);
            b1v = *(const float4*)(Wp + (size_t)(kt + 1) * 16 * CD + 4);
        }
#pragma unroll
        for (int kc = 0; kc < 16; kc += 8) {
            unsigned a[4][4], b[4][2];
#pragma unroll
            for (int mt = 0; mt < 4; mt++) {
                const int m = warp_m + mt * 16 + g;
                a[mt][0] = __float_as_uint(As[buf][kc + t][m]);
                a[mt][1] = __float_as_uint(As[buf][kc + t][m + 8]);
                a[mt][2] = __float_as_uint(As[buf][kc + t + 4][m]);
                a[mt][3] = __float_as_uint(As[buf][kc + t + 4][m + 8]);
            }
#pragma unroll
            for (int nt = 0; nt < 4; nt++) {
                const int n = warp_n + nt * 8 + g;
                b[nt][0] = __float_as_uint(Bs[buf][kc + t][n]);
                b[nt][1] = __float_as_uint(Bs[buf][kc + t + 4][n]);
            }
#pragma unroll
            for (int mt = 0; mt < 4; mt++)
#pragma unroll
                for (int nt = 0; nt < 4; nt++)
                    mma_tf32(c[mt][nt], a[mt][0], a[mt][1], a[mt][2], a[mt][3],
                             b[nt][0], b[nt][1]);
        }
        if (kt < 63) {
            buf ^= 1;
            As[buf][acol + 0][arow] = to_tf32(a0v.x);
            As[buf][acol + 1][arow] = to_tf32(a0v.y);
            As[buf][acol + 2][arow] = to_tf32(a0v.z);
            As[buf][acol + 3][arow] = to_tf32(a0v.w);
            As[buf][acol + 4][arow] = to_tf32(a1v.x);
            As[buf][acol + 5][arow] = to_tf32(a1v.y);
            As[buf][acol + 6][arow] = to_tf32(a1v.z);
            As[buf][acol + 7][arow] = to_tf32(a1v.w);
            float4 t0 = make_float4(to_tf32(b0v.x), to_tf32(b0v.y), to_tf32(b0v.z), to_tf32(b0v.w));
            float4 t1 = make_float4(to_tf32(b1v.x), to_tf32(b1v.y), to_tf32(b1v.z), to_tf32(b1v.w));
            *(float4*)&Bs[buf][wkr][wnc]     = t0;
            *(float4*)&Bs[buf][wkr][wnc + 4] = t1;
        }
        __syncthreads();
    }

#pragma unroll
    for (int mt = 0; mt < 4; mt++) {
#pragma unroll
        for (int nt = 0; nt < 4; nt++) {
            const int row = m0 + warp_m + mt * 16 + g;
            const int col = n0 + warp_n + nt * 8 + 2 * t;
            const float bx = bias[col], by = bias[col + 1];
            float2 r0 = make_float2(c[mt][nt][0] + bx, c[mt][nt][1] + by);
            float2 r1 = make_float2(c[mt][nt][2] + bx, c[mt][nt][3] + by);
            if (LAYOUT == 0) {
                *(float2*)&out[(size_t)row * CD + col]       = r0;
                *(float2*)&out[(size_t)(row + 8) * CD + col] = r1;
            } else {
                const int h = col >> 6, d = col & 63;
                {
                    const int b = row >> 11, s = row & 2047;
                    *(float2*)&out[(((size_t)(b * CH + h)) * CS + s) * CDH + d] = r0;
                }
                {
                    const int b = (row + 8) >> 11, s = (row + 8) & 2047;
                    *(float2*)&out[(((size_t)(b * CH + h)) * CS + s) * CDH + d] = r1;
                }
            }
        }
    }
}

__global__ __launch_bounds__(256) void proj_kernel(
    const float* __restrict__ x,
    const float* __restrict__ Wq, const float* __restrict__ bq,
    const float* __restrict__ Wk, const float* __restrict__ bk,
    const float* __restrict__ Wv, const float* __restrict__ bv)
{
    const float* W; const float* bias; float* out;
    if (blockIdx.z == 0)      { W = Wq; bias = bq; out = g_q; }
    else if (blockIdx.z == 1) { W = Wk; bias = bk; out = g_k; }
    else                      { W = Wv; bias = bv; out = g_v; }
    gemm_tf32<1>(x, W, bias, out);
}

__global__ __launch_bounds__(256) void outproj_kernel(
    const float* __restrict__ Wo, const float* __restrict__ bo,
    float* __restrict__ out)
{
    gemm_tf32<0>(g_o, Wo, bo, out);
}

// ---------------------------------------------------------------------------
// Tensor-core attention with FRAGMENT-PACKED smem layouts.
// A-fragments (Q, P): float4 per (kcblk, mrow, g, t) -> one LDS.128.
// B-fragments (K, V): float2 per (kcblk, ncol8, g, t) -> one LDS.64.
// Swizzle tsw = t ^ (g&3) + odd strides keep loads coalesced, stores ~2-way.
// Union region R: [KhF | KlF] during S-gemm, then [Sp | PF] afterwards.
// Math bit-identical to R4 (3xTF32 S-gemm, exact reference recurrence, single
// tf32 PV). jb > qb blocks skipped (exact no-ops).
// ---------------------------------------------------------------------------
// float offsets in dynamic smem
#define QH_OFF   0
#define QL_OFF   4128
#define R_OFF    8256
#define VF_OFF   16768
#define FSM_OFF  21024
#define ATTN_SMEM_FLOATS 21088
// inside R:
#define KL_ROFF  4256      // KlF starts here (floats, rel to R)
#define PF_ROFF  4288      // PF starts here (floats, rel to R); Sp = R[0..4224)

// A-type (float4) fragment base (in floats): stride 129 float4 per kcblk
__device__ __forceinline__ int qidx(int kcblk, int mrow, int g, int tsw) {
    return (kcblk * 129 + mrow * 32 + g * 4 + tsw) * 4;
}
// B-type (float2) fragment base (in floats): 33 f2 per ncol8, 266 f2 per kcblk
__device__ __forceinline__ int kidx(int kcblk, int ncol8, int g, int tsw) {
    return (kcblk * 266 + ncol8 * 33 + g * 4 + tsw) * 2;
}

__global__ __launch_bounds__(256) void attn_kernel()
{
    extern __shared__ float sm[];
    float* QhF = sm + QH_OFF;
    float* QlF = sm + QL_OFF;
    float* Rg  = sm + R_OFF;
    float* VF  = sm + VF_OFF;
    float* fsm = sm + FSM_OFF;

    const int qb  = blockIdx.x;
    const int bh  = blockIdx.y;
    const int tid = threadIdx.x;
    // mma layout
    const int lane = tid & 31, wid = tid >> 5;
    const int g = lane >> 2, t = lane & 3;
    const int tsw = t ^ (g & 3);
    const int wm = (wid >> 2) * 32;       // 0 / 32
    const int wn = (wid & 3) * 16;        // 0,16,32,48
    // softmax layout
    const int tx = tid & 15, ty = tid >> 4;
    // loader layout
    const int lr = tid >> 2, lc = (tid & 3) * 16;

    const size_t base = (size_t)bh * CS * CDH;
    const float* qp = g_q + base + (size_t)qb * 64 * CDH;

    // ---- Load Q (scaled 0.125), hi/lo tf32 split, packed A-fragment layout ----
    {
        const int gq = lr & 7, vm = (lr >> 3) & 1, mrow = lr >> 4;
#pragma unroll
        for (int i = 0; i < 4; i++) {
            float4 v = *(const float4*)&qp[lr * 64 + lc + i * 4];
            float xs[4] = {v.x * 0.125f, v.y * 0.125f, v.z * 0.125f, v.w * 0.125f};
#pragma unroll
            for (int j = 0; j < 4; j++) {
                const int k = lc + i * 4 + j;
                const int kcblk = k >> 3, tt = k & 3, khalf = (k >> 2) & 1;
                const int fl = qidx(kcblk, mrow, gq, tt ^ (gq & 3)) + khalf * 2 + vm;
                float h = to_tf32(xs[j]);
                QhF[fl] = h;
                QlF[fl] = to_tf32(xs[j] - h);
            }
        }
    }

    float m_reg[4], l_reg[4];
    float oc[2][2][4];
#pragma unroll
    for (int i = 0; i < 4; i++) { m_reg[i] = -3.0e38f; l_reg[i] = 0.f; }
#pragma unroll
    for (int mt = 0; mt < 2; mt++)
#pragma unroll
        for (int nt = 0; nt < 2; nt++)
#pragma unroll
            for (int r = 0; r < 4; r++) oc[mt][nt][r] = 0.f;

    for (int jb = 0; jb <= qb; jb++) {
        const float* kp = g_k + base + (size_t)jb * 64 * CDH;
        const float* vp = g_v + base + (size_t)jb * 64 * CDH;
        __syncthreads();   // (1) prev iter done reading R (PF) and VF

        // ---- Load K (hi/lo) into R[KhF|KlF]; V into VF ----
        {
            // K: row lr = seq index n, cols = head dim d
            const int gk = lr & 7, nc8 = lr >> 3;
#pragma unroll
            for (int i = 0; i < 4; i++) {
                float4 v = *(const float4*)&kp[lr * 64 + lc + i * 4];
                float xs[4] = {v.x, v.y, v.z, v.w};
#pragma unroll
                for (int j = 0; j < 4; j++) {
                    const int d = lc + i * 4 + j;
                    const int kcblk = d >> 3, tt = d & 3, khalf = (d >> 2) & 1;
                    const int fl = kidx(kcblk, nc8, gk, tt ^ (gk & 3)) + khalf;
                    float h = to_tf32(xs[j]);
                    Rg[fl]           = h;
                    Rg[KL_ROFF + fl] = to_tf32(xs[j] - h);
                }
            }
            // V: row lr = seq index k, cols = head dim n
            const int kcblk = lr >> 3, tt = lr & 3, khalf = (lr >> 2) & 1;
#pragma unroll
            for (int i = 0; i < 4; i++) {
                float4 v = *(const float4*)&vp[lr * 64 + lc + i * 4];
                float xs[4] = {v.x, v.y, v.z, v.w};
#pragma unroll
                for (int j = 0; j < 4; j++) {
                    const int n = lc + i * 4 + j;
                    const int gv = n & 7, nc8v = n >> 3;
                    const int fl = kidx(kcblk, nc8v, gv, tt ^ (gv & 3)) + khalf;
                    VF[fl] = to_tf32(xs[j]);
                }
            }
        }
        __syncthreads();   // (2)

        // ---- S = Q @ K^T, 3xTF32, packed fragment loads ----
        float sc[2][2][4];
#pragma unroll
        for (int mt = 0; mt < 2; mt++)
#pragma unroll
            for (int nt = 0; nt < 2; nt++)
#pragma unroll
                for (int r = 0; r < 4; r++) sc[mt][nt][r] = 0.f;

#pragma unroll
        for (int kcblk = 0; kcblk < 8; kcblk++) {
            float4 ah[2], al[2];
            float2 bh[2], bl[2];
#pragma unroll
            for (int mt = 0; mt < 2; mt++) {
                const int fl = qidx(kcblk, (wm >> 4) + mt, g, tsw);
                ah[mt] = *(const float4*)&QhF[fl];
                al[mt] = *(const float4*)&QlF[fl];
            }
#pragma unroll
            for (int nt = 0; nt < 2; nt++) {
                const int fl = kidx(kcblk, (wn >> 3) + nt, g, tsw);
                bh[nt] = *(const float2*)&Rg[fl];
                bl[nt] = *(const float2*)&Rg[KL_ROFF + fl];
            }
#pragma unroll
            for (int mt = 0; mt < 2; mt++)
#pragma unroll
                for (int nt = 0; nt < 2; nt++) {
                    mma_tf32(sc[mt][nt],
                             __float_as_uint(ah[mt].x), __float_as_uint(ah[mt].y),
                             __float_as_uint(ah[mt].z), __float_as_uint(ah[mt].w),
                             __float_as_uint(bh[nt].x), __float_as_uint(bh[nt].y));
                    mma_tf32(sc[mt][nt],
                             __float_as_uint(ah[mt].x), __float_as_uint(ah[mt].y),
                             __float_as_uint(ah[mt].z), __float_as_uint(ah[mt].w),
                             __float_as_uint(bl[nt].x), __float_as_uint(bl[nt].y));
                    mma_tf32(sc[mt][nt],
                             __float_as_uint(al[mt].x), __float_as_uint(al[mt].y),
                             __float_as_uint(al[mt].z), __float_as_uint(al[mt].w),
                             __float_as_uint(bh[nt].x), __float_as_uint(bh[nt].y));
                }
        }
        __syncthreads();   // (3) all warps done reading KhF/KlF

        // ---- Write S scores into Sp (row-major [64][66], overlays KhF) ----
#pragma unroll
        for (int mt = 0; mt < 2; mt++)
#pragma unroll
            for (int nt = 0; nt < 2; nt++) {
                const int row = wm + mt * 16 + g;
                const int col = wn + nt * 8 + 2 * t;
                Rg[row * 66 + col]           = sc[mt][nt][0];
                Rg[row * 66 + col + 1]       = sc[mt][nt][1];
                Rg[(row + 8) * 66 + col]     = sc[mt][nt][2];
                Rg[(row + 8) * 66 + col + 1] = sc[mt][nt][3];
            }
        __syncthreads();   // (4)

        // ---- softmax / recurrence (exact reference math, fp32) ----
#pragma unroll
        for (int i = 0; i < 4; i++) {
            const int row = ty * 4 + i;
            float s[4];
#pragma unroll
            for (int j = 0; j < 4; j++) {
                s[j] = Rg[row * 66 + tx * 4 + j];
                if (jb == qb && (tx * 4 + j) > row) s[j] = -3.0e38f;
            }
            float mx = fmaxf(fmaxf(s[0], s[1]), fmaxf(s[2], s[3]));
#pragma unroll
            for (int o = 8; o >= 1; o >>= 1)
                mx = fmaxf(mx, __shfl_xor_sync(0xffffffffu, mx, o, 16));
            const float m_new = fmaxf(m_reg[i], mx);
            const float alpha = __expf(m_reg[i] - m_new);
            float p[4], rs = 0.f;
#pragma unroll
            for (int j = 0; j < 4; j++) { p[j] = __expf(s[j] - m_new); rs += p[j]; }
#pragma unroll
            for (int o = 8; o >= 1; o >>= 1)
                rs += __shfl_xor_sync(0xffffffffu, rs, o, 16);
            const float l_new = alpha * l_reg[i] + rs;
            const float f = alpha * l_reg[i] / l_new;   // 0 on first live block
            m_reg[i] = m_new;
            l_reg[i] = l_new;
            // write P in packed A-fragment layout (PF overlays KlF region)
            const int gp = row & 7, vm = (row >> 3) & 1, mrow = row >> 4;
#pragma unroll
            for (int j = 0; j < 4; j++) {
                const int col = tx * 4 + j;
                const int kcblk = col >> 3, tt = col & 3, khalf = (col >> 2) & 1;
                const int fl = qidx(kcblk, mrow, gp, tt ^ (gp & 3)) + khalf * 2 + vm;
                Rg[PF_ROFF + fl] = to_tf32(p[j]);
            }
            if (tx == 0) fsm[row] = f;
        }
        __syncthreads();   // (5)

        // ---- O = O * f + P @ V ----
#pragma unroll
        for (int mt = 0; mt < 2; mt++) {
            const float f0 = fsm[wm + mt * 16 + g];
            const float f1 = fsm[wm + mt * 16 + g + 8];
#pragma unroll
            for (int nt = 0; nt < 2; nt++) {
                oc[mt][nt][0] *= f0; oc[mt][nt][1] *= f0;
                oc[mt][nt][2] *= f1; oc[mt][nt][3] *= f1;
            }
        }
#pragma unroll
        for (int kcblk = 0; kcblk < 8; kcblk++) {
            float4 a[2];
            float2 b[2];
#pragma unroll
            for (int mt = 0; mt < 2; mt++) {
                const int fl = qidx(kcblk, (wm >> 4) + mt, g, tsw);
                a[mt] = *(const float4*)&Rg[PF_ROFF + fl];
            }
#pragma unroll
            for (int nt = 0; nt < 2; nt++) {
                const int fl = kidx(kcblk, (wn >> 3) + nt, g, tsw);
                b[nt] = *(const float2*)&VF[fl];
            }
#pragma unroll
            for (int mt = 0; mt < 2; mt++)
#pragma unroll
                for (int nt = 0; nt < 2; nt++)
                    mma_tf32(oc[mt][nt],
                             __float_as_uint(a[mt].x), __float_as_uint(a[mt].y),
                             __float_as_uint(a[mt].z), __float_as_uint(a[mt].w),
                             __float_as_uint(b[nt].x), __float_as_uint(b[nt].y));
        }
    }

    // Write O to g_o (B,S,D): row = qb*64 + ..., col = h*64 + ...
    const int b = bh >> 4, h = bh & 15;
#pragma unroll
    for (int mt = 0; mt < 2; mt++)
#pragma unroll
        for (int nt = 0; nt < 2; nt++) {
            const int row = qb * 64 + wm + mt * 16 + g;
            const int col = h * 64 + wn + nt * 8 + 2 * t;
            *(float2*)&g_o[((size_t)b * CS + row) * CD + col] =
                make_float2(oc[mt][nt][0], oc[mt][nt][1]);
            *(float2*)&g_o[((size_t)b * CS + row + 8) * CD + col] =
                make_float2(oc[mt][nt][2], oc[mt][nt][3]);
        }
}

// ---------------------------------------------------------------------------
extern "C" void kernel_launch(void* const* d_in, const int* in_sizes, int n_in,
                              void* d_out, int out_size)
{
    const float* x  = (const float*)d_in[0];
    const float* Wq = (const float*)d_in[1];
    const float* bq = (const float*)d_in[2];
    const float* Wk = (const float*)d_in[3];
    const float* bk = (const float*)d_in[4];
    const float* Wv = (const float*)d_in[5];
    const float* bv = (const float*)d_in[6];
    const float* Wo = (const float*)d_in[7];
    const float* bo = (const float*)d_in[8];
    float* out = (float*)d_out;

    dim3 gproj(CD / 128, (CB * CS) / 128, 3);   // 8 x 64 x 3
    proj_kernel<<<gproj, 256>>>(x, Wq, bq, Wk, bk, Wv, bv);

    const size_t attn_smem = ATTN_SMEM_FLOATS * sizeof(float);
    cudaFuncSetAttribute(attn_kernel, cudaFuncAttributeMaxDynamicSharedMemorySize,
                         (int)attn_smem);
    dim3 gattn(CS / 64, CB * CH);               // 32 x 64
    attn_kernel<<<gattn, 256, attn_smem>>>();

    dim3 gout(CD / 128, (CB * CS) / 128);       // 8 x 64
    outproj_kernel<<<gout, 256>>>(Wo, bo, out);
}

// round 9
// speedup vs baseline: 1.0346x; 1.0346x over previous
#include <cuda_runtime.h>

#define CB 4
#define CS 2048
#define CD 1024
#define CH 16
#define CDH 64

// Scratch (static __device__ globals: the sanctioned no-alloc workaround).
__device__ float g_q[CB * CH * CS * CDH];   // (B,H,S,DH)
__device__ float g_k[CB * CH * CS * CDH];
__device__ float g_v[CB * CH * CS * CDH];
__device__ float g_o[CB * CS * CD];         // attention out, (B,S,D)

__device__ __forceinline__ float to_tf32(float x) {
    unsigned u;
    asm("cvt.rna.tf32.f32 %0, %1;" : "=r"(u) : "f"(x));
    return __uint_as_float(u);
}

__device__ __forceinline__ void mma_tf32(float c[4], unsigned a0, unsigned a1,
                                         unsigned a2, unsigned a3,
                                         unsigned b0, unsigned b1) {
    asm volatile(
        "mma.sync.aligned.m16n8k8.row.col.f32.tf32.tf32.f32 "
        "{%0,%1,%2,%3}, {%4,%5,%6,%7}, {%8,%9}, {%0,%1,%2,%3};\n"
        : "+f"(c[0]), "+f"(c[1]), "+f"(c[2]), "+f"(c[3])
        : "r"(a0), "r"(a1), "r"(a2), "r"(a3), "r"(b0), "r"(b1));
}

// ---------------------------------------------------------------------------
// tf32 tensor-core GEMM (unchanged from R3/R4 passing kernel).
// ---------------------------------------------------------------------------
template <int LAYOUT>
__device__ __forceinline__ void gemm_tf32(
    const float* __restrict__ A, const float* __restrict__ W,
    const float* __restrict__ bias, float* __restrict__ out)
{
    __shared__ float As[2][16][136];
    __shared__ float Bs[2][16][136];

    const int tid = threadIdx.x;
    const int m0 = blockIdx.y * 128;
    const int n0 = blockIdx.x * 128;

    const int arow  = tid & 127;
    const int acol  = (tid >> 7) * 8;
    const int wkr   = tid >> 4;
    const int wnc   = (tid & 15) * 8;

    const float* Ap = A + (size_t)(m0 + arow) * CD + acol;
    const float* Wp = W + (size_t)wkr * CD + n0 + wnc;

    {
        float4 a0v = *(const float4*)(Ap);
        float4 a1v = *(const float4*)(Ap + 4);
        float4 b0v = *(const float4*)(Wp);
        float4 b1v = *(const float4*)(Wp + 4);
        As[0][acol + 0][arow] = to_tf32(a0v.x);
        As[0][acol + 1][arow] = to_tf32(a0v.y);
        As[0][acol + 2][arow] = to_tf32(a0v.z);
        As[0][acol + 3][arow] = to_tf32(a0v.w);
        As[0][acol + 4][arow] = to_tf32(a1v.x);
        As[0][acol + 5][arow] = to_tf32(a1v.y);
        As[0][acol + 6][arow] = to_tf32(a1v.z);
        As[0][acol + 7][arow] = to_tf32(a1v.w);
        float4 t0 = make_float4(to_tf32(b0v.x), to_tf32(b0v.y), to_tf32(b0v.z), to_tf32(b0v.w));
        float4 t1 = make_float4(to_tf32(b1v.x), to_tf32(b1v.y), to_tf32(b1v.z), to_tf32(b1v.w));
        *(float4*)&Bs[0][wkr][wnc]     = t0;
        *(float4*)&Bs[0][wkr][wnc + 4] = t1;
    }
    __syncthreads();

    const int wid    = tid >> 5;
    const int lane   = tid & 31;
    const int warp_m = (wid >> 2) * 64;
    const int warp_n = (wid & 3) * 32;
    const int g = lane >> 2;
    const int t = lane & 3;

    float c[4][4][4];
#pragma unroll
    for (int mt = 0; mt < 4; mt++)
#pragma unroll
        for (int nt = 0; nt < 4; nt++)
#pragma unroll
            for (int r = 0; r < 4; r++) c[mt][nt][r] = 0.f;

    int buf = 0;
    for (int kt = 0; kt < 64; kt++) {
        float4 a0v, a1v, b0v, b1v;
        if (kt < 63) {
            a0v = *(const float4*)(Ap + (kt + 1) * 16);
            a1v = *(const float4*)(Ap + (kt + 1) * 16 + 4);
            b0v = *(const float4*)(Wp + (size_t)(kt + 1) * 16 * CD);
            b1v = *(const float4*)(Wp + (size_t)(kt + 1) * 16 * CD + 4);
        }
#pragma unroll
        for (int kc = 0; kc < 16; kc += 8) {
            unsigned a[4][4], b[4][2];
#pragma unroll
            for (int mt = 0; mt < 4; mt++) {
                const int m = warp_m + mt * 16 + g;
                a[mt][0] = __float_as_uint(As[buf][kc + t][m]);
                a[mt][1] = __float_as_uint(As[buf][kc + t][m + 8]);
                a[mt][2] = __float_as_uint(As[buf][kc + t + 4][m]);
                a[mt][3] = __float_as_uint(As[buf][kc + t + 4][m + 8]);
            }
#pragma unroll
            for (int nt = 0; nt < 4; nt++) {
                const int n = warp_n + nt * 8 + g;
                b[nt][0] = __float_as_uint(Bs[buf][kc + t][n]);
                b[nt][1] = __float_as_uint(Bs[buf][kc + t + 4][n]);
            }
#pragma unroll
            for (int mt = 0; mt < 4; mt++)
#pragma unroll
                for (int nt = 0; nt < 4; nt++)
                    mma_tf32(c[mt][nt], a[mt][0], a[mt][1], a[mt][2], a[mt][3],
                             b[nt][0], b[nt][1]);
        }
        if (kt < 63) {
            buf ^= 1;
            As[buf][acol + 0][arow] = to_tf32(a0v.x);
            As[buf][acol + 1][arow] = to_tf32(a0v.y);
            As[buf][acol + 2][arow] = to_tf32(a0v.z);
            As[buf][acol + 3][arow] = to_tf32(a0v.w);
            As[buf][acol + 4][arow] = to_tf32(a1v.x);
            As[buf][acol + 5][arow] = to_tf32(a1v.y);
            As[buf][acol + 6][arow] = to_tf32(a1v.z);
            As[buf][acol + 7][arow] = to_tf32(a1v.w);
            float4 t0 = make_float4(to_tf32(b0v.x), to_tf32(b0v.y), to_tf32(b0v.z), to_tf32(b0v.w));
            float4 t1 = make_float4(to_tf32(b1v.x), to_tf32(b1v.y), to_tf32(b1v.z), to_tf32(b1v.w));
            *(float4*)&Bs[buf][wkr][wnc]     = t0;
            *(float4*)&Bs[buf][wkr][wnc + 4] = t1;
        }
        __syncthreads();
    }

#pragma unroll
    for (int mt = 0; mt < 4; mt++) {
#pragma unroll
        for (int nt = 0; nt < 4; nt++) {
            const int row = m0 + warp_m + mt * 16 + g;
            const int col = n0 + warp_n + nt * 8 + 2 * t;
            const float bx = bias[col], by = bias[col + 1];
            float2 r0 = make_float2(c[mt][nt][0] + bx, c[mt][nt][1] + by);
            float2 r1 = make_float2(c[mt][nt][2] + bx, c[mt][nt][3] + by);
            if (LAYOUT == 0) {
                *(float2*)&out[(size_t)row * CD + col]       = r0;
                *(float2*)&out[(size_t)(row + 8) * CD + col] = r1;
            } else {
                const int h = col >> 6, d = col & 63;
                {
                    const int b = row >> 11, s = row & 2047;
                    *(float2*)&out[(((size_t)(b * CH + h)) * CS + s) * CDH + d] = r0;
                }
                {
                    const int b = (row + 8) >> 11, s = (row + 8) & 2047;
                    *(float2*)&out[(((size_t)(b * CH + h)) * CS + s) * CDH + d] = r1;
                }
            }
        }
    }
}

__global__ __launch_bounds__(256) void proj_kernel(
    const float* __restrict__ x,
    const float* __restrict__ Wq, const float* __restrict__ bq,
    const float* __restrict__ Wk, const float* __restrict__ bk,
    const float* __restrict__ Wv, const float* __restrict__ bv)
{
    const float* W; const float* bias; float* out;
    if (blockIdx.z == 0)      { W = Wq; bias = bq; out = g_q; }
    else if (blockIdx.z == 1) { W = Wk; bias = bk; out = g_k; }
    else                      { W = Wv; bias = bv; out = g_v; }
    gemm_tf32<1>(x, W, bias, out);
}

__global__ __launch_bounds__(256) void outproj_kernel(
    const float* __restrict__ Wo, const float* __restrict__ bo,
    float* __restrict__ out)
{
    gemm_tf32<0>(g_o, Wo, bo, out);
}

// ---------------------------------------------------------------------------
// Attention v3: warp-owned rows, register-resident softmax.
// CTA = 128 threads (4 warps), one 64-row q-tile; warp w owns rows
// [w*16, w*16+16). Grid (32, 64). Per jb-block (2 syncthreads only):
//   sync; load K(hi/lo) + V into packed B-fragment smem; sync;
//   S = Q@K^T (3xTF32, Q hi/lo in REGISTERS with log2e folded into scale);
//   mask/max/exp2/sum in C-fragment registers (quad shfl-xor 1,2);
//   P repacked C->A fragment via quad shfls; O = O*f + P@V (tf32).
// Recurrence math identical to reference (exp(x)=exp2(x*log2e), no final
// normalization); jb > qb blocks are exact no-ops -> skipped.
// ---------------------------------------------------------------------------
#define KREG 4256   // floats per packed B-fragment region
// B-type (float2) fragment base (in floats): 33 f2 per ncol8, 266 f2 per kcblk
__device__ __forceinline__ int kidx(int kcblk, int ncol8, int g, int tsw) {
    return (kcblk * 266 + ncol8 * 33 + g * 4 + tsw) * 2;
}

__global__ __launch_bounds__(128, 2) void attn_kernel()
{
    extern __shared__ float smf[];
    float* KhF = smf;              // [0, 4256)
    float* KlF = smf + KREG;       // [4256, 8512)
    float* VF  = smf + 2 * KREG;   // [8512, 12768)

    const int qb  = blockIdx.x;
    const int bh  = blockIdx.y;
    const int tid = threadIdx.x;
    const int lane = tid & 31, w = tid >> 5;
    const int g = lane >> 2, t = lane & 3;
    const int tsw = t ^ (g & 3);
    const int srcA = (lane & ~3) | (t >> 1);   // quad lane holding col t
    const int srcB = srcA + 2;                 // quad lane holding col t+4
    const bool sel = (t & 1) != 0;

    const size_t base = (size_t)bh * CS * CDH;
    const float* qp = g_q + base + (size_t)qb * 64 * CDH;

    // ---- Q into registers: scale 0.125*log2(e), hi/lo tf32 split ----
    const float QS = 0.125f * 1.4426950408889634f;
    const int r0 = w * 16 + g, r1 = r0 + 8;
    float qh[8][4], ql[8][4];
#pragma unroll
    for (int kb = 0; kb < 8; kb++) {
        float xs[4];
        xs[0] = qp[r0 * 64 + kb * 8 + t] * QS;
        xs[1] = qp[r1 * 64 + kb * 8 + t] * QS;
        xs[2] = qp[r0 * 64 + kb * 8 + t + 4] * QS;
        xs[3] = qp[r1 * 64 + kb * 8 + t + 4] * QS;
#pragma unroll
        for (int i = 0; i < 4; i++) {
            float h = to_tf32(xs[i]);
            qh[kb][i] = h;
            ql[kb][i] = to_tf32(xs[i] - h);
        }
    }

    float m0 = -3.0e38f, m1 = -3.0e38f, l0 = 0.f, l1 = 0.f;
    float oc[8][4];
#pragma unroll
    for (int nt = 0; nt < 8; nt++)
#pragma unroll
        for (int r = 0; r < 4; r++) oc[nt][r] = 0.f;

    // loader indices (128 threads: 2 threads per 64-col row)
    const int lr = tid >> 1;            // 0..63
    const int lc = (tid & 1) * 32;      // 0 or 32
    const int gk = lr & 7, nc8 = lr >> 3;              // K row decomposition
    const int vkb = lr >> 3, vtt = lr & 3, vkh = (lr >> 2) & 1;  // V row

    for (int jb = 0; jb <= qb; jb++) {
        const float* kp = g_k + base + (size_t)jb * 64 * CDH;
        const float* vp = g_v + base + (size_t)jb * 64 * CDH;
        __syncthreads();   // (1) prev iter done reading KhF/KlF/VF

        // ---- K hi/lo + V into packed B-fragment smem ----
#pragma unroll
        for (int i = 0; i < 8; i++) {
            float4 v = *(const float4*)&kp[lr * 64 + lc + i * 4];
            float xs[4] = {v.x, v.y, v.z, v.w};
#pragma unroll
            for (int j = 0; j < 4; j++) {
                const int d = lc + i * 4 + j;
                const int fl = kidx(d >> 3, nc8, gk, (d & 3) ^ (gk & 3)) + ((d >> 2) & 1);
                float h = to_tf32(xs[j]);
                KhF[fl] = h;
                KlF[fl] = to_tf32(xs[j] - h);
            }
        }
#pragma unroll
        for (int i = 0; i < 8; i++) {
            float4 v = *(const float4*)&vp[lr * 64 + lc + i * 4];
            float xs[4] = {v.x, v.y, v.z, v.w};
#pragma unroll
            for (int j = 0; j < 4; j++) {
                const int n = lc + i * 4 + j;
                const int gv = n & 7, nc8v = n >> 3;
                VF[kidx(vkb, nc8v, gv, vtt ^ (gv & 3)) + vkh] = to_tf32(xs[j]);
            }
        }
        __syncthreads();   // (2) tiles visible

        // ---- S = Q @ K^T (3xTF32), C-fragments in registers ----
        float sc[8][4];
#pragma unroll
        for (int nt = 0; nt < 8; nt++)
#pragma unroll
            for (int r = 0; r < 4; r++) sc[nt][r] = 0.f;

#pragma unroll
        for (int kc = 0; kc < 8; kc++) {
            const unsigned a0 = __float_as_uint(qh[kc][0]), a1 = __float_as_uint(qh[kc][1]);
            const unsigned a2 = __float_as_uint(qh[kc][2]), a3 = __float_as_uint(qh[kc][3]);
            const unsigned e0 = __float_as_uint(ql[kc][0]), e1 = __float_as_uint(ql[kc][1]);
            const unsigned e2 = __float_as_uint(ql[kc][2]), e3 = __float_as_uint(ql[kc][3]);
#pragma unroll
            for (int nt = 0; nt < 8; nt++) {
                const int fl = kidx(kc, nt, g, tsw);
                float2 bhv = *(const float2*)&KhF[fl];
                float2 blv = *(const float2*)&KlF[fl];
                const unsigned b0 = __float_as_uint(bhv.x), b1 = __float_as_uint(bhv.y);
                const unsigned c0 = __float_as_uint(blv.x), c1 = __float_as_uint(blv.y);
                mma_tf32(sc[nt], a0, a1, a2, a3, b0, b1);
                mma_tf32(sc[nt], a0, a1, a2, a3, c0, c1);
                mma_tf32(sc[nt], e0, e1, e2, e3, b0, b1);
            }
        }

        // ---- mask (diagonal block only) ----
        if (jb == qb) {
            const int rl0 = w * 16 + g, rl1 = rl0 + 8;
#pragma unroll
            for (int nt = 0; nt < 8; nt++) {
                const int c0col = nt * 8 + 2 * t;
                if (c0col > rl0)     sc[nt][0] = -3.0e38f;
                if (c0col + 1 > rl0) sc[nt][1] = -3.0e38f;
                if (c0col > rl1)     sc[nt][2] = -3.0e38f;
                if (c0col + 1 > rl1) sc[nt][3] = -3.0e38f;
            }
        }

        // ---- softmax / recurrence in registers (rows g and g+8) ----
        float mx0 = -3.0e38f, mx1 = -3.0e38f;
#pragma unroll
        for (int nt = 0; nt < 8; nt++) {
            mx0 = fmaxf(mx0, fmaxf(sc[nt][0], sc[nt][1]));
            mx1 = fmaxf(mx1, fmaxf(sc[nt][2], sc[nt][3]));
        }
        mx0 = fmaxf(mx0, __shfl_xor_sync(0xffffffffu, mx0, 1));
        mx0 = fmaxf(mx0, __shfl_xor_sync(0xffffffffu, mx0, 2));
        mx1 = fmaxf(mx1, __shfl_xor_sync(0xffffffffu, mx1, 1));
        mx1 = fmaxf(mx1, __shfl_xor_sync(0xffffffffu, mx1, 2));

        const float mn0 = fmaxf(m0, mx0), mn1 = fmaxf(m1, mx1);
        const float al0 = exp2f(m0 - mn0), al1 = exp2f(m1 - mn1);
        float rs0 = 0.f, rs1 = 0.f;
#pragma unroll
        for (int nt = 0; nt < 8; nt++) {
            float p0 = exp2f(sc[nt][0] - mn0);
            float p1 = exp2f(sc[nt][1] - mn0);
            float p2 = exp2f(sc[nt][2] - mn1);
            float p3 = exp2f(sc[nt][3] - mn1);
            rs0 += p0 + p1;
            rs1 += p2 + p3;
            sc[nt][0] = to_tf32(p0);
            sc[nt][1] = to_tf32(p1);
            sc[nt][2] = to_tf32(p2);
            sc[nt][3] = to_tf32(p3);
        }
        rs0 += __shfl_xor_sync(0xffffffffu, rs0, 1);
        rs0 += __shfl_xor_sync(0xffffffffu, rs0, 2);
        rs1 += __shfl_xor_sync(0xffffffffu, rs1, 1);
        rs1 += __shfl_xor_sync(0xffffffffu, rs1, 2);

        const float ln0 = al0 * l0 + rs0, ln1 = al1 * l1 + rs1;
        const float f0 = al0 * l0 / ln0, f1 = al1 * l1 / ln1;  // 0 on first block
        m0 = mn0; m1 = mn1; l0 = ln0; l1 = ln1;

#pragma unroll
        for (int nt = 0; nt < 8; nt++) {
            oc[nt][0] *= f0; oc[nt][1] *= f0;
            oc[nt][2] *= f1; oc[nt][3] *= f1;
        }

        // ---- O += P @ V : repack P (C->A frag via quad shfls), mma ----
#pragma unroll
        for (int kb = 0; kb < 8; kb++) {
            float u0 = __shfl_sync(0xffffffffu, sc[kb][0], srcA);
            float u1 = __shfl_sync(0xffffffffu, sc[kb][1], srcA);
            float v0 = __shfl_sync(0xffffffffu, sc[kb][2], srcA);
            float v1 = __shfl_sync(0xffffffffu, sc[kb][3], srcA);
            float w0 = __shfl_sync(0xffffffffu, sc[kb][0], srcB);
            float w1 = __shfl_sync(0xffffffffu, sc[kb][1], srcB);
            float x0 = __shfl_sync(0xffffffffu, sc[kb][2], srcB);
            float x1 = __shfl_sync(0xffffffffu, sc[kb][3], srcB);
            const unsigned a0 = __float_as_uint(sel ? u1 : u0);
            const unsigned a1 = __float_as_uint(sel ? v1 : v0);
            const unsigned a2 = __float_as_uint(sel ? w1 : w0);
            const unsigned a3 = __float_as_uint(sel ? x1 : x0);
#pragma unroll
            for (int nt = 0; nt < 8; nt++) {
                const int fl = kidx(kb, nt, g, tsw);
                float2 bv = *(const float2*)&VF[fl];
                mma_tf32(oc[nt], a0, a1, a2, a3,
                         __float_as_uint(bv.x), __float_as_uint(bv.y));
            }
        }
    }

    // ---- Write O to g_o (B,S,D) ----
    const int b = bh >> 4, h = bh & 15;
    const int row0 = qb * 64 + w * 16 + g;
#pragma unroll
    for (int nt = 0; nt < 8; nt++) {
        const int col = h * 64 + nt * 8 + 2 * t;
        *(float2*)&g_o[((size_t)b * CS + row0) * CD + col] =
            make_float2(oc[nt][0], oc[nt][1]);
        *(float2*)&g_o[((size_t)b * CS + row0 + 8) * CD + col] =
            make_float2(oc[nt][2], oc[nt][3]);
    }
}

// ---------------------------------------------------------------------------
extern "C" void kernel_launch(void* const* d_in, const int* in_sizes, int n_in,
                              void* d_out, int out_size)
{
    const float* x  = (const float*)d_in[0];
    const float* Wq = (const float*)d_in[1];
    const float* bq = (const float*)d_in[2];
    const float* Wk = (const float*)d_in[3];
    const float* bk = (const float*)d_in[4];
    const float* Wv = (const float*)d_in[5];
    const float* bv = (const float*)d_in[6];
    const float* Wo = (const float*)d_in[7];
    const float* bo = (const float*)d_in[8];
    float* out = (float*)d_out;

    dim3 gproj(CD / 128, (CB * CS) / 128, 3);   // 8 x 64 x 3
    proj_kernel<<<gproj, 256>>>(x, Wq, bq, Wk, bk, Wv, bv);

    const size_t attn_smem = 3 * KREG * sizeof(float);   // ~51 KB
    cudaFuncSetAttribute(attn_kernel, cudaFuncAttributeMaxDynamicSharedMemorySize,
                         (int)attn_smem);
    dim3 gattn(CS / 64, CB * CH);               // 32 x 64
    attn_kernel<<<gattn, 128, attn_smem>>>();

    dim3 gout(CD / 128, (CB * CS) / 128);       // 8 x 64
    outproj_kernel<<<gout, 256>>>(Wo, bo, out);
}

// round 10
// speedup vs baseline: 1.0369x; 1.0023x over previous
#include <cuda_runtime.h>

#define CB 4
#define CS 2048
#define CD 1024
#define CH 16
#define CDH 64

// Scratch (static __device__ globals: the sanctioned no-alloc workaround).
__device__ float g_q[CB * CH * CS * CDH];   // (B,H,S,DH)
__device__ float g_k[CB * CH * CS * CDH];
__device__ float g_v[CB * CH * CS * CDH];
__device__ float g_o[CB * CS * CD];         // attention out, (B,S,D)

__device__ __forceinline__ float to_tf32(float x) {
    unsigned u;
    asm("cvt.rna.tf32.f32 %0, %1;" : "=r"(u) : "f"(x));
    return __uint_as_float(u);
}

__device__ __forceinline__ void mma_tf32(float c[4], unsigned a0, unsigned a1,
                                         unsigned a2, unsigned a3,
                                         unsigned b0, unsigned b1) {
    asm volatile(
        "mma.sync.aligned.m16n8k8.row.col.f32.tf32.tf32.f32 "
        "{%0,%1,%2,%3}, {%4,%5,%6,%7}, {%8,%9}, {%0,%1,%2,%3};\n"
        : "+f"(c[0]), "+f"(c[1]), "+f"(c[2]), "+f"(c[3])
        : "r"(a0), "r"(a1), "r"(a2), "r"(a3), "r"(b0), "r"(b1));
}

// ---------------------------------------------------------------------------
// tf32 tensor-core GEMM (unchanged from R3/R4 passing kernel).
// ---------------------------------------------------------------------------
template <int LAYOUT>
__device__ __forceinline__ void gemm_tf32(
    const float* __restrict__ A, const float* __restrict__ W,
    const float* __restrict__ bias, float* __restrict__ out)
{
    __shared__ float As[2][16][136];
    __shared__ float Bs[2][16][136];

    const int tid = threadIdx.x;
    const int m0 = blockIdx.y * 128;
    const int n0 = blockIdx.x * 128;

    const int arow  = tid & 127;
    const int acol  = (tid >> 7) * 8;
    const int wkr   = tid >> 4;
    const int wnc   = (tid & 15) * 8;

    const float* Ap = A + (size_t)(m0 + arow) * CD + acol;
    const float* Wp = W + (size_t)wkr * CD + n0 + wnc;

    {
        float4 a0v = *(const float4*)(Ap);
        float4 a1v = *(const float4*)(Ap + 4);
        float4 b0v = *(const float4*)(Wp);
        float4 b1v = *(const float4*)(Wp + 4);
        As[0][acol + 0][arow] = to_tf32(a0v.x);
        As[0][acol + 1][arow] = to_tf32(a0v.y);
        As[0][acol + 2][arow] = to_tf32(a0v.z);
        As[0][acol + 3][arow] = to_tf32(a0v.w);
        As[0][acol + 4][arow] = to_tf32(a1v.x);
        As[0][acol + 5][arow] = to_tf32(a1v.y);
        As[0][acol + 6][arow] = to_tf32(a1v.z);
        As[0][acol + 7][arow] = to_tf32(a1v.w);
        float4 t0 = make_float4(to_tf32(b0v.x), to_tf32(b0v.y), to_tf32(b0v.z), to_tf32(b0v.w));
        float4 t1 = make_float4(to_tf32(b1v.x), to_tf32(b1v.y), to_tf32(b1v.z), to_tf32(b1v.w));
        *(float4*)&Bs[0][wkr][wnc]     = t0;
        *(float4*)&Bs[0][wkr][wnc + 4] = t1;
    }
    __syncthreads();

    const int wid    = tid >> 5;
    const int lane   = tid & 31;
    const int warp_m = (wid >> 2) * 64;
    const int warp_n = (wid & 3) * 32;
    const int g = lane >> 2;
    const int t = lane & 3;

    float c[4][4][4];
#pragma unroll
    for (int mt = 0; mt < 4; mt++)
#pragma unroll
        for (int nt = 0; nt < 4; nt++)
#pragma unroll
            for (int r = 0; r < 4; r++) c[mt][nt][r] = 0.f;

    int buf = 0;
    for (int kt = 0; kt < 64; kt++) {
        float4 a0v, a1v, b0v, b1v;
        if (kt < 63) {
            a0v = *(const float4*)(Ap + (kt + 1) * 16);
            a1v = *(const float4*)(Ap + (kt + 1) * 16 + 4);
            b0v = *(const float4*)(Wp + (size_t)(kt + 1) * 16 * CD);
            b1v = *(const float4*)(Wp + (size_t)(kt + 1) * 16 * CD + 4);
        }
#pragma unroll
        for (int kc = 0; kc < 16; kc += 8) {
            unsigned a[4][4], b[4][2];
#pragma unroll
            for (int mt = 0; mt < 4; mt++) {
                const int m = warp_m + mt * 16 + g;
                a[mt][0] = __float_as_uint(As[buf][kc + t][m]);
                a[mt][1] = __float_as_uint(As[buf][kc + t][m + 8]);
                a[mt][2] = __float_as_uint(As[buf][kc + t + 4][m]);
                a[mt][3] = __float_as_uint(As[buf][kc + t + 4][m + 8]);
            }
#pragma unroll
            for (int nt = 0; nt < 4; nt++) {
                const int n = warp_n + nt * 8 + g;
                b[nt][0] = __float_as_uint(Bs[buf][kc + t][n]);
                b[nt][1] = __float_as_uint(Bs[buf][kc + t + 4][n]);
            }
#pragma unroll
            for (int mt = 0; mt < 4; mt++)
#pragma unroll
                for (int nt = 0; nt < 4; nt++)
                    mma_tf32(c[mt][nt], a[mt][0], a[mt][1], a[mt][2], a[mt][3],
                             b[nt][0], b[nt][1]);
        }
        if (kt < 63) {
            buf ^= 1;
            As[buf][acol + 0][arow] = to_tf32(a0v.x);
            As[buf][acol + 1][arow] = to_tf32(a0v.y);
            As[buf][acol + 2][arow] = to_tf32(a0v.z);
            As[buf][acol + 3][arow] = to_tf32(a0v.w);
            As[buf][acol + 4][arow] = to_tf32(a1v.x);
            As[buf][acol + 5][arow] = to_tf32(a1v.y);
            As[buf][acol + 6][arow] = to_tf32(a1v.z);
            As[buf][acol + 7][arow] = to_tf32(a1v.w);
            float4 t0 = make_float4(to_tf32(b0v.x), to_tf32(b0v.y), to_tf32(b0v.z), to_tf32(b0v.w));
            float4 t1 = make_float4(to_tf32(b1v.x), to_tf32(b1v.y), to_tf32(b1v.z), to_tf32(b1v.w));
            *(float4*)&Bs[buf][wkr][wnc]     = t0;
            *(float4*)&Bs[buf][wkr][wnc + 4] = t1;
        }
        __syncthreads();
    }

#pragma unroll
    for (int mt = 0; mt < 4; mt++) {
#pragma unroll
        for (int nt = 0; nt < 4; nt++) {
            const int row = m0 + warp_m + mt * 16 + g;
            const int col = n0 + warp_n + nt * 8 + 2 * t;
            const float bx = bias[col], by = bias[col + 1];
            float2 r0 = make_float2(c[mt][nt][0] + bx, c[mt][nt][1] + by);
            float2 r1 = make_float2(c[mt][nt][2] + bx, c[mt][nt][3] + by);
            if (LAYOUT == 0) {
                *(float2*)&out[(size_t)row * CD + col]       = r0;
                *(float2*)&out[(size_t)(row + 8) * CD + col] = r1;
            } else {
                const int h = col >> 6, d = col & 63;
                {
                    const int b = row >> 11, s = row & 2047;
                    *(float2*)&out[(((size_t)(b * CH + h)) * CS + s) * CDH + d] = r0;
                }
                {
                    const int b = (row + 8) >> 11, s = (row + 8) & 2047;
                    *(float2*)&out[(((size_t)(b * CH + h)) * CS + s) * CDH + d] = r1;
                }
            }
        }
    }
}

__global__ __launch_bounds__(256) void proj_kernel(
    const float* __restrict__ x,
    const float* __restrict__ Wq, const float* __restrict__ bq,
    const float* __restrict__ Wk, const float* __restrict__ bk,
    const float* __restrict__ Wv, const float* __restrict__ bv)
{
    const float* W; const float* bias; float* out;
    if (blockIdx.z == 0)      { W = Wq; bias = bq; out = g_q; }
    else if (blockIdx.z == 1) { W = Wk; bias = bk; out = g_k; }
    else                      { W = Wv; bias = bv; out = g_v; }
    gemm_tf32<1>(x, W, bias, out);
}

__global__ __launch_bounds__(256) void outproj_kernel(
    const float* __restrict__ Wo, const float* __restrict__ bo,
    float* __restrict__ out)
{
    gemm_tf32<0>(g_o, Wo, bo, out);
}

// ---------------------------------------------------------------------------
// Attention v3: warp-owned rows, register-resident softmax.
// CTA = 128 threads (4 warps), one 64-row q-tile; warp w owns rows
// [w*16, w*16+16). Grid (32, 64). Per jb-block (2 syncthreads only):
//   sync; load K(hi/lo) + V into packed B-fragment smem; sync;
//   S = Q@K^T (3xTF32, Q hi/lo in REGISTERS with log2e folded into scale);
//   mask/max/exp2/sum in C-fragment registers (quad shfl-xor 1,2);
//   P repacked C->A fragment via quad shfls; O = O*f + P@V (tf32).
// Recurrence math identical to reference (exp(x)=exp2(x*log2e), no final
// normalization); jb > qb blocks are exact no-ops -> skipped.
// ---------------------------------------------------------------------------
#define KREG 4256   // floats per packed B-fragment region
// B-type (float2) fragment base (in floats): 33 f2 per ncol8, 266 f2 per kcblk
__device__ __forceinline__ int kidx(int kcblk, int ncol8, int g, int tsw) {
    return (kcblk * 266 + ncol8 * 33 + g * 4 + tsw) * 2;
}

__global__ __launch_bounds__(128, 2) void attn_kernel()
{
    extern __shared__ float smf[];
    float* KhF = smf;              // [0, 4256)
    float* KlF = smf + KREG;       // [4256, 8512)
    float* VF  = smf + 2 * KREG;   // [8512, 12768)

    const int qb  = blockIdx.x;
    const int bh  = blockIdx.y;
    const int tid = threadIdx.x;
    const int lane = tid & 31, w = tid >> 5;
    const int g = lane >> 2, t = lane & 3;
    const int tsw = t ^ (g & 3);
    const int srcA = (lane & ~3) | (t >> 1);   // quad lane holding col t
    const int srcB = srcA + 2;                 // quad lane holding col t+4
    const bool sel = (t & 1) != 0;

    const size_t base = (size_t)bh * CS * CDH;
    const float* qp = g_q + base + (size_t)qb * 64 * CDH;

    // ---- Q into registers: scale 0.125*log2(e), hi/lo tf32 split ----
    const float QS = 0.125f * 1.4426950408889634f;
    const int r0 = w * 16 + g, r1 = r0 + 8;
    float qh[8][4], ql[8][4];
#pragma unroll
    for (int kb = 0; kb < 8; kb++) {
        float xs[4];
        xs[0] = qp[r0 * 64 + kb * 8 + t] * QS;
        xs[1] = qp[r1 * 64 + kb * 8 + t] * QS;
        xs[2] = qp[r0 * 64 + kb * 8 + t + 4] * QS;
        xs[3] = qp[r1 * 64 + kb * 8 + t + 4] * QS;
#pragma unroll
        for (int i = 0; i < 4; i++) {
            float h = to_tf32(xs[i]);
            qh[kb][i] = h;
            ql[kb][i] = to_tf32(xs[i] - h);
        }
    }

    float m0 = -3.0e38f, m1 = -3.0e38f, l0 = 0.f, l1 = 0.f;
    float oc[8][4];
#pragma unroll
    for (int nt = 0; nt < 8; nt++)
#pragma unroll
        for (int r = 0; r < 4; r++) oc[nt][r] = 0.f;

    // loader indices (128 threads: 2 threads per 64-col row)
    const int lr = tid >> 1;            // 0..63
    const int lc = (tid & 1) * 32;      // 0 or 32
    const int gk = lr & 7, nc8 = lr >> 3;              // K row decomposition
    const int vkb = lr >> 3, vtt = lr & 3, vkh = (lr >> 2) & 1;  // V row

    for (int jb = 0; jb <= qb; jb++) {
        const float* kp = g_k + base + (size_t)jb * 64 * CDH;
        const float* vp = g_v + base + (size_t)jb * 64 * CDH;
        __syncthreads();   // (1) prev iter done reading KhF/KlF/VF

        // ---- K hi/lo + V into packed B-fragment smem ----
#pragma unroll
        for (int i = 0; i < 8; i++) {
            float4 v = *(const float4*)&kp[lr * 64 + lc + i * 4];
            float xs[4] = {v.x, v.y, v.z, v.w};
#pragma unroll
            for (int j = 0; j < 4; j++) {
                const int d = lc + i * 4 + j;
                const int fl = kidx(d >> 3, nc8, gk, (d & 3) ^ (gk & 3)) + ((d >> 2) & 1);
                float h = to_tf32(xs[j]);
                KhF[fl] = h;
                KlF[fl] = to_tf32(xs[j] - h);
            }
        }
#pragma unroll
        for (int i = 0; i < 8; i++) {
            float4 v = *(const float4*)&vp[lr * 64 + lc + i * 4];
            float xs[4] = {v.x, v.y, v.z, v.w};
#pragma unroll
            for (int j = 0; j < 4; j++) {
                const int n = lc + i * 4 + j;
                const int gv = n & 7, nc8v = n >> 3;
                VF[kidx(vkb, nc8v, gv, vtt ^ (gv & 3)) + vkh] = to_tf32(xs[j]);
            }
        }
        __syncthreads();   // (2) tiles visible

        // ---- S = Q @ K^T (3xTF32), C-fragments in registers ----
        float sc[8][4];
#pragma unroll
        for (int nt = 0; nt < 8; nt++)
#pragma unroll
            for (int r = 0; r < 4; r++) sc[nt][r] = 0.f;

#pragma unroll
        for (int kc = 0; kc < 8; kc++) {
            const unsigned a0 = __float_as_uint(qh[kc][0]), a1 = __float_as_uint(qh[kc][1]);
            const unsigned a2 = __float_as_uint(qh[kc][2]), a3 = __float_as_uint(qh[kc][3]);
            const unsigned e0 = __float_as_uint(ql[kc][0]), e1 = __float_as_uint(ql[kc][1]);
            const unsigned e2 = __float_as_uint(ql[kc][2]), e3 = __float_as_uint(ql[kc][3]);
#pragma unroll
            for (int nt = 0; nt < 8; nt++) {
                const int fl = kidx(kc, nt, g, tsw);
                float2 bhv = *(const float2*)&KhF[fl];
                float2 blv = *(const float2*)&KlF[fl];
                const unsigned b0 = __float_as_uint(bhv.x), b1 = __float_as_uint(bhv.y);
                const unsigned c0 = __float_as_uint(blv.x), c1 = __float_as_uint(blv.y);
                mma_tf32(sc[nt], a0, a1, a2, a3, b0, b1);
                mma_tf32(sc[nt], a0, a1, a2, a3, c0, c1);
                mma_tf32(sc[nt], e0, e1, e2, e3, b0, b1);
            }
        }

        // ---- mask (diagonal block only) ----
        if (jb == qb) {
            const int rl0 = w * 16 + g, rl1 = rl0 + 8;
#pragma unroll
            for (int nt = 0; nt < 8; nt++) {
                const int c0col = nt * 8 + 2 * t;
                if (c0col > rl0)     sc[nt][0] = -3.0e38f;
                if (c0col + 1 > rl0) sc[nt][1] = -3.0e38f;
                if (c0col > rl1)     sc[nt][2] = -3.0e38f;
                if (c0col + 1 > rl1) sc[nt][3] = -3.0e38f;
            }
        }

        // ---- softmax / recurrence in registers (rows g and g+8) ----
        float mx0 = -3.0e38f, mx1 = -3.0e38f;
#pragma unroll
        for (int nt = 0; nt < 8; nt++) {
            mx0 = fmaxf(mx0, fmaxf(sc[nt][0], sc[nt][1]));
            mx1 = fmaxf(mx1, fmaxf(sc[nt][2], sc[nt][3]));
        }
        mx0 = fmaxf(mx0, __shfl_xor_sync(0xffffffffu, mx0, 1));
        mx0 = fmaxf(mx0, __shfl_xor_sync(0xffffffffu, mx0, 2));
        mx1 = fmaxf(mx1, __shfl_xor_sync(0xffffffffu, mx1, 1));
        mx1 = fmaxf(mx1, __shfl_xor_sync(0xffffffffu, mx1, 2));

        const float mn0 = fmaxf(m0, mx0), mn1 = fmaxf(m1, mx1);
        const float al0 = exp2f(m0 - mn0), al1 = exp2f(m1 - mn1);
        float rs0 = 0.f, rs1 = 0.f;
#pragma unroll
        for (int nt = 0; nt < 8; nt++) {
            float p0 = exp2f(sc[nt][0] - mn0);
            float p1 = exp2f(sc[nt][1] - mn0);
            float p2 = exp2f(sc[nt][2] - mn1);
            float p3 = exp2f(sc[nt][3] - mn1);
            rs0 += p0 + p1;
            rs1 += p2 + p3;
            sc[nt][0] = to_tf32(p0);
            sc[nt][1] = to_tf32(p1);
            sc[nt][2] = to_tf32(p2);
            sc[nt][3] = to_tf32(p3);
        }
        rs0 += __shfl_xor_sync(0xffffffffu, rs0, 1);
        rs0 += __shfl_xor_sync(0xffffffffu, rs0, 2);
        rs1 += __shfl_xor_sync(0xffffffffu, rs1, 1);
        rs1 += __shfl_xor_sync(0xffffffffu, rs1, 2);

        const float ln0 = al0 * l0 + rs0, ln1 = al1 * l1 + rs1;
        const float f0 = al0 * l0 / ln0, f1 = al1 * l1 / ln1;  // 0 on first block
        m0 = mn0; m1 = mn1; l0 = ln0; l1 = ln1;

#pragma unroll
        for (int nt = 0; nt < 8; nt++) {
            oc[nt][0] *= f0; oc[nt][1] *= f0;
            oc[nt][2] *= f1; oc[nt][3] *= f1;
        }

        // ---- O += P @ V : repack P (C->A frag via quad shfls), mma ----
#pragma unroll
        for (int kb = 0; kb < 8; kb++) {
            float u0 = __shfl_sync(0xffffffffu, sc[kb][0], srcA);
            float u1 = __shfl_sync(0xffffffffu, sc[kb][1], srcA);
            float v0 = __shfl_sync(0xffffffffu, sc[kb][2], srcA);
            float v1 = __shfl_sync(0xffffffffu, sc[kb][3], srcA);
            float w0 = __shfl_sync(0xffffffffu, sc[kb][0], srcB);
            float w1 = __shfl_sync(0xffffffffu, sc[kb][1], srcB);
            float x0 = __shfl_sync(0xffffffffu, sc[kb][2], srcB);
            float x1 = __shfl_sync(0xffffffffu, sc[kb][3], srcB);
            const unsigned a0 = __float_as_uint(sel ? u1 : u0);
            const unsigned a1 = __float_as_uint(sel ? v1 : v0);
            const unsigned a2 = __float_as_uint(sel ? w1 : w0);
            const unsigned a3 = __float_as_uint(sel ? x1 : x0);
#pragma unroll
            for (int nt = 0; nt < 8; nt++) {
                const int fl = kidx(kb, nt, g, tsw);
                float2 bv = *(const float2*)&VF[fl];
                mma_tf32(oc[nt], a0, a1, a2, a3,
                         __float_as_uint(bv.x), __float_as_uint(bv.y));
            }
        }
    }

    // ---- Write O to g_o (B,S,D) ----
    const int b = bh >> 4, h = bh & 15;
    const int row0 = qb * 64 + w * 16 + g;
#pragma unroll
    for (int nt = 0; nt < 8; nt++) {
        const int col = h * 64 + nt * 8 + 2 * t;
        *(float2*)&g_o[((size_t)b * CS + row0) * CD + col] =
            make_float2(oc[nt][0], oc[nt][1]);
        *(float2*)&g_o[((size_t)b * CS + row0 + 8) * CD + col] =
            make_float2(oc[nt][2], oc[nt][3]);
    }
}

// ---------------------------------------------------------------------------
extern "C" void kernel_launch(void* const* d_in, const int* in_sizes, int n_in,
                              void* d_out, int out_size)
{
    const float* x  = (const float*)d_in[0];
    const float* Wq = (const float*)d_in[1];
    const float* bq = (const float*)d_in[2];
    const float* Wk = (const float*)d_in[3];
    const float* bk = (const float*)d_in[4];
    const float* Wv = (const float*)d_in[5];
    const float* bv = (const float*)d_in[6];
    const float* Wo = (const float*)d_in[7];
    const float* bo = (const float*)d_in[8];
    float* out = (float*)d_out;

    dim3 gproj(CD / 128, (CB * CS) / 128, 3);   // 8 x 64 x 3
    proj_kernel<<<gproj, 256>>>(x, Wq, bq, Wk, bk, Wv, bv);

    const size_t attn_smem = 3 * KREG * sizeof(float);   // ~51 KB
    cudaFuncSetAttribute(attn_kernel, cudaFuncAttributeMaxDynamicSharedMemorySize,
                         (int)attn_smem);
    dim3 gattn(CS / 64, CB * CH);               // 32 x 64
    attn_kernel<<<gattn, 128, attn_smem>>>();

    dim3 gout(CD / 128, (CB * CS) / 128);       // 8 x 64
    outproj_kernel<<<gout, 256>>>(Wo, bo, out);
}

// round 11
// speedup vs baseline: 1.0395x; 1.0025x over previous
#include <cuda_runtime.h>

#define CB 4
#define CS 2048
#define CD 1024
#define CH 16
#define CDH 64

// Scratch (static __device__ globals: the sanctioned no-alloc workaround).
__device__ float g_q[CB * CH * CS * CDH];   // (B,H,S,DH)
__device__ float g_k[CB * CH * CS * CDH];
__device__ float g_v[CB * CH * CS * CDH];
__device__ float g_o[CB * CS * CD];         // attention out, (B,S,D)

__device__ __forceinline__ float to_tf32(float x) {
    unsigned u;
    asm("cvt.rna.tf32.f32 %0, %1;" : "=r"(u) : "f"(x));
    return __uint_as_float(u);
}

__device__ __forceinline__ void mma_tf32(float c[4], unsigned a0, unsigned a1,
                                         unsigned a2, unsigned a3,
                                         unsigned b0, unsigned b1) {
    asm volatile(
        "mma.sync.aligned.m16n8k8.row.col.f32.tf32.tf32.f32 "
        "{%0,%1,%2,%3}, {%4,%5,%6,%7}, {%8,%9}, {%0,%1,%2,%3};\n"
        : "+f"(c[0]), "+f"(c[1]), "+f"(c[2]), "+f"(c[3])
        : "r"(a0), "r"(a1), "r"(a2), "r"(a3), "r"(b0), "r"(b1));
}

// ---------------------------------------------------------------------------
// tf32 tensor-core GEMM (unchanged from R3/R4 passing kernel).
// ---------------------------------------------------------------------------
template <int LAYOUT>
__device__ __forceinline__ void gemm_tf32(
    const float* __restrict__ A, const float* __restrict__ W,
    const float* __restrict__ bias, float* __restrict__ out)
{
    __shared__ float As[2][16][136];
    __shared__ float Bs[2][16][136];

    const int tid = threadIdx.x;
    const int m0 = blockIdx.y * 128;
    const int n0 = blockIdx.x * 128;

    const int arow  = tid & 127;
    const int acol  = (tid >> 7) * 8;
    const int wkr   = tid >> 4;
    const int wnc   = (tid & 15) * 8;

    const float* Ap = A + (size_t)(m0 + arow) * CD + acol;
    const float* Wp = W + (size_t)wkr * CD + n0 + wnc;

    {
        float4 a0v = *(const float4*)(Ap);
        float4 a1v = *(const float4*)(Ap + 4);
        float4 b0v = *(const float4*)(Wp);
        float4 b1v = *(const float4*)(Wp + 4);
        As[0][acol + 0][arow] = to_tf32(a0v.x);
        As[0][acol + 1][arow] = to_tf32(a0v.y);
        As[0][acol + 2][arow] = to_tf32(a0v.z);
        As[0][acol + 3][arow] = to_tf32(a0v.w);
        As[0][acol + 4][arow] = to_tf32(a1v.x);
        As[0][acol + 5][arow] = to_tf32(a1v.y);
        As[0][acol + 6][arow] = to_tf32(a1v.z);
        As[0][acol + 7][arow] = to_tf32(a1v.w);
        float4 t0 = make_float4(to_tf32(b0v.x), to_tf32(b0v.y), to_tf32(b0v.z), to_tf32(b0v.w));
        float4 t1 = make_float4(to_tf32(b1v.x), to_tf32(b1v.y), to_tf32(b1v.z), to_tf32(b1v.w));
        *(float4*)&Bs[0][wkr][wnc]     = t0;
        *(float4*)&Bs[0][wkr][wnc + 4] = t1;
    }
    __syncthreads();

    const int wid    = tid >> 5;
    const int lane   = tid & 31;
    const int warp_m = (wid >> 2) * 64;
    const int warp_n = (wid & 3) * 32;
    const int g = lane >> 2;
    const int t = lane & 3;

    float c[4][4][4];
#pragma unroll
    for (int mt = 0; mt < 4; mt++)
#pragma unroll
        for (int nt = 0; nt < 4; nt++)
#pragma unroll
            for (int r = 0; r < 4; r++) c[mt][nt][r] = 0.f;

    int buf = 0;
    for (int kt = 0; kt < 64; kt++) {
        float4 a0v, a1v, b0v, b1v;
        if (kt < 63) {
            a0v = *(const float4*)(Ap + (kt + 1) * 16);
            a1v = *(const float4*)(Ap + (kt + 1) * 16 + 4);
            b0v = *(const float4*)(Wp + (size_t)(kt + 1) * 16 * CD);
            b1v = *(const float4*)(Wp + (size_t)(kt + 1) * 16 * CD + 4);
        }
#pragma unroll
        for (int kc = 0; kc < 16; kc += 8) {
            unsigned a[4][4], b[4][2];
#pragma unroll
            for (int mt = 0; mt < 4; mt++) {
                const int m = warp_m + mt * 16 + g;
                a[mt][0] = __float_as_uint(As[buf][kc + t][m]);
                a[mt][1] = __float_as_uint(As[buf][kc + t][m + 8]);
                a[mt][2] = __float_as_uint(As[buf][kc + t + 4][m]);
                a[mt][3] = __float_as_uint(As[buf][kc + t + 4][m + 8]);
            }
#pragma unroll
            for (int nt = 0; nt < 4; nt++) {
                const int n = warp_n + nt * 8 + g;
                b[nt][0] = __float_as_uint(Bs[buf][kc + t][n]);
                b[nt][1] = __float_as_uint(Bs[buf][kc + t + 4][n]);
            }
#pragma unroll
            for (int mt = 0; mt < 4; mt++)
#pragma unroll
                for (int nt = 0; nt < 4; nt++)
                    mma_tf32(c[mt][nt], a[mt][0], a[mt][1], a[mt][2], a[mt][3],
                             b[nt][0], b[nt][1]);
        }
        if (kt < 63) {
            buf ^= 1;
            As[buf][acol + 0][arow] = to_tf32(a0v.x);
            As[buf][acol + 1][arow] = to_tf32(a0v.y);
            As[buf][acol + 2][arow] = to_tf32(a0v.z);
            As[buf][acol + 3][arow] = to_tf32(a0v.w);
            As[buf][acol + 4][arow] = to_tf32(a1v.x);
            As[buf][acol + 5][arow] = to_tf32(a1v.y);
            As[buf][acol + 6][arow] = to_tf32(a1v.z);
            As[buf][acol + 7][arow] = to_tf32(a1v.w);
            float4 t0 = make_float4(to_tf32(b0v.x), to_tf32(b0v.y), to_tf32(b0v.z), to_tf32(b0v.w));
            float4 t1 = make_float4(to_tf32(b1v.x), to_tf32(b1v.y), to_tf32(b1v.z), to_tf32(b1v.w));
            *(float4*)&Bs[buf][wkr][wnc]     = t0;
            *(float4*)&Bs[buf][wkr][wnc + 4] = t1;
        }
        __syncthreads();
    }

#pragma unroll
    for (int mt = 0; mt < 4; mt++) {
#pragma unroll
        for (int nt = 0; nt < 4; nt++) {
            const int row = m0 + warp_m + mt * 16 + g;
            const int col = n0 + warp_n + nt * 8 + 2 * t;
            const float bx = bias[col], by = bias[col + 1];
            float2 r0 = make_float2(c[mt][nt][0] + bx, c[mt][nt][1] + by);
            float2 r1 = make_float2(c[mt][nt][2] + bx, c[mt][nt][3] + by);
            if (LAYOUT == 0) {
                *(float2*)&out[(size_t)row * CD + col]       = r0;
                *(float2*)&out[(size_t)(row + 8) * CD + col] = r1;
            } else {
                const int h = col >> 6, d = col & 63;
                {
                    const int b = row >> 11, s = row & 2047;
                    *(float2*)&out[(((size_t)(b * CH + h)) * CS + s) * CDH + d] = r0;
                }
                {
                    const int b = (row + 8) >> 11, s = (row + 8) & 2047;
                    *(float2*)&out[(((size_t)(b * CH + h)) * CS + s) * CDH + d] = r1;
                }
            }
        }
    }
}

__global__ __launch_bounds__(256) void proj_kernel(
    const float* __restrict__ x,
    const float* __restrict__ Wq, const float* __restrict__ bq,
    const float* __restrict__ Wk, const float* __restrict__ bk,
    const float* __restrict__ Wv, const float* __restrict__ bv)
{
    const float* W; const float* bias; float* out;
    if (blockIdx.z == 0)      { W = Wq; bias = bq; out = g_q; }
    else if (blockIdx.z == 1) { W = Wk; bias = bk; out = g_k; }
    else                      { W = Wv; bias = bv; out = g_v; }
    gemm_tf32<1>(x, W, bias, out);
}

__global__ __launch_bounds__(256) void outproj_kernel(
    const float* __restrict__ Wo, const float* __restrict__ bo,
    float* __restrict__ out)
{
    gemm_tf32<0>(g_o, Wo, bo, out);
}

// ---------------------------------------------------------------------------
// Attention v3: warp-owned rows, register-resident softmax.
// CTA = 128 threads (4 warps), one 64-row q-tile; warp w owns rows
// [w*16, w*16+16). Grid (32, 64). Per jb-block (2 syncthreads only):
//   sync; load K(hi/lo) + V into packed B-fragment smem; sync;
//   S = Q@K^T (3xTF32, Q hi/lo in REGISTERS with log2e folded into scale);
//   mask/max/exp2/sum in C-fragment registers (quad shfl-xor 1,2);
//   P repacked C->A fragment via quad shfls; O = O*f + P@V (tf32).
// Recurrence math identical to reference (exp(x)=exp2(x*log2e), no final
// normalization); jb > qb blocks are exact no-ops -> skipped.
// ---------------------------------------------------------------------------
#define KREG 4256   // floats per packed B-fragment region
// B-type (float2) fragment base (in floats): 33 f2 per ncol8, 266 f2 per kcblk
__device__ __forceinline__ int kidx(int kcblk, int ncol8, int g, int tsw) {
    return (kcblk * 266 + ncol8 * 33 + g * 4 + tsw) * 2;
}

__global__ __launch_bounds__(128, 2) void attn_kernel()
{
    extern __shared__ float smf[];
    float* KhF = smf;              // [0, 4256)
    float* KlF = smf + KREG;       // [4256, 8512)
    float* VF  = smf + 2 * KREG;   // [8512, 12768)

    const int qb  = blockIdx.x;
    const int bh  = blockIdx.y;
    const int tid = threadIdx.x;
    const int lane = tid & 31, w = tid >> 5;
    const int g = lane >> 2, t = lane & 3;
    const int tsw = t ^ (g & 3);
    const int srcA = (lane & ~3) | (t >> 1);   // quad lane holding col t
    const int srcB = srcA + 2;                 // quad lane holding col t+4
    const bool sel = (t & 1) != 0;

    const size_t base = (size_t)bh * CS * CDH;
    const float* qp = g_q + base + (size_t)qb * 64 * CDH;

    // ---- Q into registers: scale 0.125*log2(e), hi/lo tf32 split ----
    const float QS = 0.125f * 1.4426950408889634f;
    const int r0 = w * 16 + g, r1 = r0 + 8;
    float qh[8][4], ql[8][4];
#pragma unroll
    for (int kb = 0; kb < 8; kb++) {
        float xs[4];
        xs[0] = qp[r0 * 64 + kb * 8 + t] * QS;
        xs[1] = qp[r1 * 64 + kb * 8 + t] * QS;
        xs[2] = qp[r0 * 64 + kb * 8 + t + 4] * QS;
        xs[3] = qp[r1 * 64 + kb * 8 + t + 4] * QS;
#pragma unroll
        for (int i = 0; i < 4; i++) {
            float h = to_tf32(xs[i]);
            qh[kb][i] = h;
            ql[kb][i] = to_tf32(xs[i] - h);
        }
    }

    float m0 = -3.0e38f, m1 = -3.0e38f, l0 = 0.f, l1 = 0.f;
    float oc[8][4];
#pragma unroll
    for (int nt = 0; nt < 8; nt++)
#pragma unroll
        for (int r = 0; r < 4; r++) oc[nt][r] = 0.f;

    // loader indices (128 threads: 2 threads per 64-col row)
    const int lr = tid >> 1;            // 0..63
    const int lc = (tid & 1) * 32;      // 0 or 32
    const int gk = lr & 7, nc8 = lr >> 3;              // K row decomposition
    const int vkb = lr >> 3, vtt = lr & 3, vkh = (lr >> 2) & 1;  // V row

    for (int jb = 0; jb <= qb; jb++) {
        const float* kp = g_k + base + (size_t)jb * 64 * CDH;
        const float* vp = g_v + base + (size_t)jb * 64 * CDH;
        __syncthreads();   // (1) prev iter done reading KhF/KlF/VF

        // ---- K hi/lo + V into packed B-fragment smem ----
#pragma unroll
        for (int i = 0; i < 8; i++) {
            float4 v = *(const float4*)&kp[lr * 64 + lc + i * 4];
            float xs[4] = {v.x, v.y, v.z, v.w};
#pragma unroll
            for (int j = 0; j < 4; j++) {
                const int d = lc + i * 4 + j;
                const int fl = kidx(d >> 3, nc8, gk, (d & 3) ^ (gk & 3)) + ((d >> 2) & 1);
                float h = to_tf32(xs[j]);
                KhF[fl] = h;
                KlF[fl] = to_tf32(xs[j] - h);
            }
        }
#pragma unroll
        for (int i = 0; i < 8; i++) {
            float4 v = *(const float4*)&vp[lr * 64 + lc + i * 4];
            float xs[4] = {v.x, v.y, v.z, v.w};
#pragma unroll
            for (int j = 0; j < 4; j++) {
                const int n = lc + i * 4 + j;
                const int gv = n & 7, nc8v = n >> 3;
                VF[kidx(vkb, nc8v, gv, vtt ^ (gv & 3)) + vkh] = to_tf32(xs[j]);
            }
        }
        __syncthreads();   // (2) tiles visible

        // ---- S = Q @ K^T (3xTF32), C-fragments in registers ----
        float sc[8][4];
#pragma unroll
        for (int nt = 0; nt < 8; nt++)
#pragma unroll
            for (int r = 0; r < 4; r++) sc[nt][r] = 0.f;

#pragma unroll
        for (int kc = 0; kc < 8; kc++) {
            const unsigned a0 = __float_as_uint(qh[kc][0]), a1 = __float_as_uint(qh[kc][1]);
            const unsigned a2 = __float_as_uint(qh[kc][2]), a3 = __float_as_uint(qh[kc][3]);
            const unsigned e0 = __float_as_uint(ql[kc][0]), e1 = __float_as_uint(ql[kc][1]);
            const unsigned e2 = __float_as_uint(ql[kc][2]), e3 = __float_as_uint(ql[kc][3]);
#pragma unroll
            for (int nt = 0; nt < 8; nt++) {
                const int fl = kidx(kc, nt, g, tsw);
                float2 bhv = *(const float2*)&KhF[fl];
                float2 blv = *(const float2*)&KlF[fl];
                const unsigned b0 = __float_as_uint(bhv.x), b1 = __float_as_uint(bhv.y);
                const unsigned c0 = __float_as_uint(blv.x), c1 = __float_as_uint(blv.y);
                mma_tf32(sc[nt], a0, a1, a2, a3, b0, b1);
                mma_tf32(sc[nt], a0, a1, a2, a3, c0, c1);
                mma_tf32(sc[nt], e0, e1, e2, e3, b0, b1);
            }
        }

        // ---- mask (diagonal block only) ----
        if (jb == qb) {
            const int rl0 = w * 16 + g, rl1 = rl0 + 8;
#pragma unroll
            for (int nt = 0; nt < 8; nt++) {
                const int c0col = nt * 8 + 2 * t;
                if (c0col > rl0)     sc[nt][0] = -3.0e38f;
                if (c0col + 1 > rl0) sc[nt][1] = -3.0e38f;
                if (c0col > rl1)     sc[nt][2] = -3.0e38f;
                if (c0col + 1 > rl1) sc[nt][3] = -3.0e38f;
            }
        }

        // ---- softmax / recurrence in registers (rows g and g+8) ----
        float mx0 = -3.0e38f, mx1 = -3.0e38f;
#pragma unroll
        for (int nt = 0; nt < 8; nt++) {
            mx0 = fmaxf(mx0, fmaxf(sc[nt][0], sc[nt][1]));
            mx1 = fmaxf(mx1, fmaxf(sc[nt][2], sc[nt][3]));
        }
        mx0 = fmaxf(mx0, __shfl_xor_sync(0xffffffffu, mx0, 1));
        mx0 = fmaxf(mx0, __shfl_xor_sync(0xffffffffu, mx0, 2));
        mx1 = fmaxf(mx1, __shfl_xor_sync(0xffffffffu, mx1, 1));
        mx1 = fmaxf(mx1, __shfl_xor_sync(0xffffffffu, mx1, 2));

        const float mn0 = fmaxf(m0, mx0), mn1 = fmaxf(m1, mx1);
        const float al0 = exp2f(m0 - mn0), al1 = exp2f(m1 - mn1);
        float rs0 = 0.f, rs1 = 0.f;
#pragma unroll
        for (int nt = 0; nt < 8; nt++) {
            float p0 = exp2f(sc[nt][0] - mn0);
            float p1 = exp2f(sc[nt][1] - mn0);
            float p2 = exp2f(sc[nt][2] - mn1);
            float p3 = exp2f(sc[nt][3] - mn1);
            rs0 += p0 + p1;
            rs1 += p2 + p3;
            sc[nt][0] = to_tf32(p0);
            sc[nt][1] = to_tf32(p1);
            sc[nt][2] = to_tf32(p2);
            sc[nt][3] = to_tf32(p3);
        }
        rs0 += __shfl_xor_sync(0xffffffffu, rs0, 1);
        rs0 += __shfl_xor_sync(0xffffffffu, rs0, 2);
        rs1 += __shfl_xor_sync(0xffffffffu, rs1, 1);
        rs1 += __shfl_xor_sync(0xffffffffu, rs1, 2);

        const float ln0 = al0 * l0 + rs0, ln1 = al1 * l1 + rs1;
        const float f0 = al0 * l0 / ln0, f1 = al1 * l1 / ln1;  // 0 on first block
        m0 = mn0; m1 = mn1; l0 = ln0; l1 = ln1;

#pragma unroll
        for (int nt = 0; nt < 8; nt++) {
            oc[nt][0] *= f0; oc[nt][1] *= f0;
            oc[nt][2] *= f1; oc[nt][3] *= f1;
        }

        // ---- O += P @ V : repack P (C->A frag via quad shfls), mma ----
#pragma unroll
        for (int kb = 0; kb < 8; kb++) {
            float u0 = __shfl_sync(0xffffffffu, sc[kb][0], srcA);
            float u1 = __shfl_sync(0xffffffffu, sc[kb][1], srcA);
            float v0 = __shfl_sync(0xffffffffu, sc[kb][2], srcA);
            float v1 = __shfl_sync(0xffffffffu, sc[kb][3], srcA);
            float w0 = __shfl_sync(0xffffffffu, sc[kb][0], srcB);
            float w1 = __shfl_sync(0xffffffffu, sc[kb][1], srcB);
            float x0 = __shfl_sync(0xffffffffu, sc[kb][2], srcB);
            float x1 = __shfl_sync(0xffffffffu, sc[kb][3], srcB);
            const unsigned a0 = __float_as_uint(sel ? u1 : u0);
            const unsigned a1 = __float_as_uint(sel ? v1 : v0);
            const unsigned a2 = __float_as_uint(sel ? w1 : w0);
            const unsigned a3 = __float_as_uint(sel ? x1 : x0);
#pragma unroll
            for (int nt = 0; nt < 8; nt++) {
                const int fl = kidx(kb, nt, g, tsw);
                float2 bv = *(const float2*)&VF[fl];
                mma_tf32(oc[nt], a0, a1, a2, a3,
                         __float_as_uint(bv.x), __float_as_uint(bv.y));
            }
        }
    }

    // ---- Write O to g_o (B,S,D) ----
    const int b = bh >> 4, h = bh & 15;
    const int row0 = qb * 64 + w * 16 + g;
#pragma unroll
    for (int nt = 0; nt < 8; nt++) {
        const int col = h * 64 + nt * 8 + 2 * t;
        *(float2*)&g_o[((size_t)b * CS + row0) * CD + col] =
            make_float2(oc[nt][0], oc[nt][1]);
        *(float2*)&g_o[((size_t)b * CS + row0 + 8) * CD + col] =
            make_float2(oc[nt][2], oc[nt][3]);
    }
}

// ---------------------------------------------------------------------------
extern "C" void kernel_launch(void* const* d_in, const int* in_sizes, int n_in,
                              void* d_out, int out_size)
{
    const float* x  = (const float*)d_in[0];
    const float* Wq = (const float*)d_in[1];
    const float* bq = (const float*)d_in[2];
    const float* Wk = (const float*)d_in[3];
    const float* bk = (const float*)d_in[4];
    const float* Wv = (const float*)d_in[5];
    const float* bv = (const float*)d_in[6];
    const float* Wo = (const float*)d_in[7];
    const float* bo = (const float*)d_in[8];
    float* out = (float*)d_out;

    dim3 gproj(CD / 128, (CB * CS) / 128, 3);   // 8 x 64 x 3
    proj_kernel<<<gproj, 256>>>(x, Wq, bq, Wk, bk, Wv, bv);

    const size_t attn_smem = 3 * KREG * sizeof(float);   // ~51 KB
    cudaFuncSetAttribute(attn_kernel, cudaFuncAttributeMaxDynamicSharedMemorySize,
                         (int)attn_smem);
    dim3 gattn(CS / 64, CB * CH);               // 32 x 64
    attn_kernel<<<gattn, 128, attn_smem>>>();

    dim3 gout(CD / 128, (CB * CS) / 128);       // 8 x 64
    outproj_kernel<<<gout, 256>>>(Wo, bo, out);
}